// round 16
// baseline (speedup 1.0000x reference)
#include <cuda_runtime.h>
#include <math.h>

// Problem constants (fixed shapes from reference)
#define NT   65536      // total nodes = 128*512
#define NE   524288     // edges (before self loops)
#define NG   128        // graphs
#define NPG  512        // nodes per graph
#define EPG  4096       // edges per graph (NE/NG)
#define KTOP 410        // ceil(0.8*512)
#define H1   64
#define H2   128
#define FIN  128
#define NC   10

#define NMASK (NT - 1)    // node index guard (power of 2)
#define EMASK (NE - 1)    // edge index guard (power of 2)

// ---------------- scratch (device globals; no runtime allocation) ----------
__device__ __align__(16) float g_dis[NT];      // rsqrt(degree), incl self loop
__device__ __align__(16) int   g_rowptr[NT];   // CSR row start (global edge idx)
__device__ __align__(16) int   g_rowend[NT];   // CSR row end
__device__ __align__(16) int   g_esrc[NE];     // CSR: src per in-edge (dst-grouped)
__device__ __align__(16) float g_h1[NT * H1];  // x @ W1
__device__ __align__(16) float g_agg1[NT * H1];// relu(conv1 out)
__device__ __align__(16) float g_h2[NT * H2];  // agg1 @ W2
__device__ __align__(16) float g_agg2[NT * H2];// relu(conv2 out)

// ---------------- per-graph CSR build: NO atomics anywhere ----------------
// edge_index is INT32 (JAX default x64-disabled: astype(int64) -> int32!).
// One block per graph. Edges of graph g live in ei[g*EPG ..), node ids in
// [g*NPG, (g+1)*NPG). Thread t owns local node t. All indirect indices are
// masked so no input data can produce an out-of-bounds access.
__global__ __launch_bounds__(512) void k_csr(const int* __restrict__ ei) {
    __shared__ __align__(16) int s_src[EPG];   // localized src, 0..511
    __shared__ __align__(16) int s_dst[EPG];   // localized dst, 0..511
    __shared__ int s_scan[NPG];
    const int g = blockIdx.x;
    const int t = threadIdx.x;
    const int ebase = g * EPG;
    const int nbase = g * NPG;

    // load edges, localize ids to 0..511 (mask guards any layout surprise)
#pragma unroll
    for (int k = 0; k < EPG / 512; k++) {
        int e = t + k * 512;
        s_src[e] = (ei[ebase + e] - nbase) & (NPG - 1);
        s_dst[e] = (ei[NE + ebase + e] - nbase) & (NPG - 1);
    }
    __syncthreads();

    // count in-degree of node t (int4 = 4 dsts per LDS.128, smem broadcast)
    int cnt = 0;
    const int4* d4 = (const int4*)s_dst;
    for (int e4 = 0; e4 < EPG / 4; e4++) {
        int4 d = d4[e4];
        cnt += (d.x == t) + (d.y == t) + (d.z == t) + (d.w == t);
    }

    // exclusive scan over 512 degrees (Hillis-Steele in smem)
    s_scan[t] = cnt;
    __syncthreads();
    for (int off = 1; off < 512; off <<= 1) {
        int v = (t >= off) ? s_scan[t - off] : 0;
        __syncthreads();
        s_scan[t] += v;
        __syncthreads();
    }
    const int rstart = ebase + s_scan[t] - cnt;
    g_rowptr[nbase + t] = rstart;
    g_rowend[nbase + t] = rstart + cnt;
    g_dis[nbase + t] = rsqrtf((float)(cnt + 1));   // +1 self loop

    // fill my row in edge order (deterministic); threads own disjoint ranges
    int pos = rstart;
    const int4* s4 = (const int4*)s_src;
    for (int e4 = 0; e4 < EPG / 4; e4++) {
        int4 d = d4[e4];
        int4 s = s4[e4];
        if (d.x == t) g_esrc[pos++ & EMASK] = nbase + s.x;
        if (d.y == t) g_esrc[pos++ & EMASK] = nbase + s.y;
        if (d.z == t) g_esrc[pos++ & EMASK] = nbase + s.z;
        if (d.w == t) g_esrc[pos++ & EMASK] = nbase + s.w;
    }
}

// ---------------- GEMM1: h1[NT,64] = x[NT,128] @ W1[128,64] ----------------
__global__ __launch_bounds__(128) void k_gemm1(const float* __restrict__ x,
                                               const float* __restrict__ W) {
    __shared__ float Xs[128][33];
    __shared__ float Ws[32][64];
    const int tid = threadIdx.x;
    const int nb = blockIdx.x * 128;

    float acc[64];
#pragma unroll
    for (int j = 0; j < 64; j++) acc[j] = 0.0f;

    for (int kc = 0; kc < 4; kc++) {   // K=128 in chunks of 32
#pragma unroll
        for (int it = 0; it < 8; it++) {
            int i = tid + it * 128;
            int row = i >> 3, q = i & 7;
            float4 v = ((const float4*)x)[(size_t)(nb + row) * 32 + kc * 8 + q];
            Xs[row][q * 4 + 0] = v.x;
            Xs[row][q * 4 + 1] = v.y;
            Xs[row][q * 4 + 2] = v.z;
            Xs[row][q * 4 + 3] = v.w;
        }
#pragma unroll
        for (int it = 0; it < 4; it++) {
            int i = tid + it * 128;
            int r = i >> 4, q = i & 15;
            float4 v = ((const float4*)W)[(size_t)(kc * 32 + r) * 16 + q];
            *(float4*)&Ws[r][q * 4] = v;
        }
        __syncthreads();

        for (int kk = 0; kk < 32; kk++) {
            float a = Xs[tid][kk];
#pragma unroll
            for (int j = 0; j < 64; j += 4) {
                float4 w4 = *(const float4*)&Ws[kk][j];
                acc[j + 0] += a * w4.x;
                acc[j + 1] += a * w4.y;
                acc[j + 2] += a * w4.z;
                acc[j + 3] += a * w4.w;
            }
        }
        __syncthreads();
    }

    float4* out = (float4*)&g_h1[(size_t)(nb + tid) * 64];
#pragma unroll
    for (int j = 0; j < 16; j++)
        out[j] = make_float4(acc[4 * j], acc[4 * j + 1], acc[4 * j + 2], acc[4 * j + 3]);
}

// ---------------- gather1: agg1 = relu(self + bias + sum_e w*h1[src]) -----
// one warp per node; lane owns float2 (2 of 64 features)
__global__ __launch_bounds__(256) void k_gather1(const float* __restrict__ b1) {
    const int node = (blockIdx.x * 256 + threadIdx.x) >> 5;
    const int lane = threadIdx.x & 31;
    const int start = g_rowptr[node] & EMASK;
    int cnt = g_rowend[node] - g_rowptr[node];
    if (cnt < 0) cnt = 0; if (cnt > EPG) cnt = EPG;
    const int end = start + cnt;
    const float dd = g_dis[node];
    const float2* h = (const float2*)g_h1;

    float2 acc = h[(size_t)node * 32 + lane];
    float2 b   = ((const float2*)b1)[lane];
    acc.x = dd * dd * acc.x + b.x;
    acc.y = dd * dd * acc.y + b.y;

    int j = start;
    while (j < end) {
        int m = end - j; if (m > 8) m = 8;
        int sa[8]; float wa[8];
#pragma unroll
        for (int k = 0; k < 8; k++) sa[k] = (k < m) ? (g_esrc[(j + k) & EMASK] & NMASK) : 0;
#pragma unroll
        for (int k = 0; k < 8; k++) wa[k] = (k < m) ? dd * g_dis[sa[k]] : 0.0f;
#pragma unroll
        for (int k = 0; k < 8; k++) {
            float2 v = h[(size_t)sa[k] * 32 + lane];
            acc.x += wa[k] * v.x;
            acc.y += wa[k] * v.y;
        }
        j += m;
    }
    ((float2*)g_agg1)[(size_t)node * 32 + lane] =
        make_float2(fmaxf(acc.x, 0.0f), fmaxf(acc.y, 0.0f));
}

// ---------------- GEMM2: h2[NT,128] = agg1[NT,64] @ W2[64,128] ------------
__global__ __launch_bounds__(128) void k_gemm2(const float* __restrict__ W2) {
    __shared__ float Xs[128][33];
    __shared__ float Ws[32][64];
    const int tid = threadIdx.x;
    const int nb = blockIdx.x * 128;
    const int cb = blockIdx.y * 64;

    float acc[64];
#pragma unroll
    for (int j = 0; j < 64; j++) acc[j] = 0.0f;

    for (int kc = 0; kc < 2; kc++) {   // K=64 in chunks of 32
#pragma unroll
        for (int it = 0; it < 8; it++) {
            int i = tid + it * 128;
            int row = i >> 3, q = i & 7;
            float4 v = ((const float4*)g_agg1)[(size_t)(nb + row) * 16 + kc * 8 + q];
            Xs[row][q * 4 + 0] = v.x;
            Xs[row][q * 4 + 1] = v.y;
            Xs[row][q * 4 + 2] = v.z;
            Xs[row][q * 4 + 3] = v.w;
        }
#pragma unroll
        for (int it = 0; it < 4; it++) {
            int i = tid + it * 128;
            int r = i >> 4, q = i & 15;
            float4 v = ((const float4*)W2)[(size_t)(kc * 32 + r) * 32 + (cb >> 2) + q];
            *(float4*)&Ws[r][q * 4] = v;
        }
        __syncthreads();

        for (int kk = 0; kk < 32; kk++) {
            float a = Xs[tid][kk];
#pragma unroll
            for (int j = 0; j < 64; j += 4) {
                float4 w4 = *(const float4*)&Ws[kk][j];
                acc[j + 0] += a * w4.x;
                acc[j + 1] += a * w4.y;
                acc[j + 2] += a * w4.z;
                acc[j + 3] += a * w4.w;
            }
        }
        __syncthreads();
    }

    float4* out = (float4*)&g_h2[(size_t)(nb + tid) * 128 + cb];
#pragma unroll
    for (int j = 0; j < 16; j++)
        out[j] = make_float4(acc[4 * j], acc[4 * j + 1], acc[4 * j + 2], acc[4 * j + 3]);
}

// ---------------- gather2: agg2 = relu(self + bias + sum_e w*h2[src]) -----
// one warp per node; lane owns float4 (4 of 128 features)
__global__ __launch_bounds__(256) void k_gather2(const float* __restrict__ b2) {
    const int node = (blockIdx.x * 256 + threadIdx.x) >> 5;
    const int lane = threadIdx.x & 31;
    const int start = g_rowptr[node] & EMASK;
    int cnt = g_rowend[node] - g_rowptr[node];
    if (cnt < 0) cnt = 0; if (cnt > EPG) cnt = EPG;
    const int end = start + cnt;
    const float dd = g_dis[node];
    const float4* h = (const float4*)g_h2;

    float4 acc = h[(size_t)node * 32 + lane];
    float4 b   = ((const float4*)b2)[lane];
    float d2 = dd * dd;
    acc.x = d2 * acc.x + b.x;
    acc.y = d2 * acc.y + b.y;
    acc.z = d2 * acc.z + b.z;
    acc.w = d2 * acc.w + b.w;

    int j = start;
    while (j < end) {
        int m = end - j; if (m > 8) m = 8;
        int sa[8]; float wa[8];
#pragma unroll
        for (int k = 0; k < 8; k++) sa[k] = (k < m) ? (g_esrc[(j + k) & EMASK] & NMASK) : 0;
#pragma unroll
        for (int k = 0; k < 8; k++) wa[k] = (k < m) ? dd * g_dis[sa[k]] : 0.0f;
#pragma unroll
        for (int k = 0; k < 8; k++) {
            float4 v = h[(size_t)sa[k] * 32 + lane];
            acc.x += wa[k] * v.x;
            acc.y += wa[k] * v.y;
            acc.z += wa[k] * v.z;
            acc.w += wa[k] * v.w;
        }
        j += m;
    }
    ((float4*)g_agg2)[(size_t)node * 32 + lane] =
        make_float4(fmaxf(acc.x, 0.0f), fmaxf(acc.y, 0.0f),
                    fmaxf(acc.z, 0.0f), fmaxf(acc.w, 0.0f));
}

// ---------------- per-graph: score, top-K threshold, gated max, FC, lsm ---
__global__ __launch_bounds__(512) void k_pool(const float* __restrict__ pw,
                                              const float* __restrict__ fcW,
                                              const float* __restrict__ fcb,
                                              float* __restrict__ out) {
    __shared__ float pwsh[128];
    __shared__ float sc[NPG];
    __shared__ float so[NPG];
    __shared__ float gsh[128];
    __shared__ float lg[NC];
    __shared__ float red2[2];
    __shared__ float s_inv;

    const int tid = threadIdx.x;
    const int g = blockIdx.x;

    if (tid < 128) pwsh[tid] = pw[tid];
    __syncthreads();
    if (tid == 0) {
        float s = 0.0f;
        for (int f = 0; f < 128; f++) s += pwsh[f] * pwsh[f];
        s_inv = rsqrtf(s);
    }
    __syncthreads();

    // score for my node = dot(agg2_row, pw) / ||pw||   (agg2 already relu'd)
    {
        const float4* row = (const float4*)(g_agg2 + (size_t)(g * NPG + tid) * 128);
        float s = 0.0f;
#pragma unroll 8
        for (int i = 0; i < 32; i++) {
            float4 v = row[i];
            s += v.x * pwsh[4 * i + 0] + v.y * pwsh[4 * i + 1]
               + v.z * pwsh[4 * i + 2] + v.w * pwsh[4 * i + 3];
        }
        s *= s_inv;
        sc[tid] = s;
        so[tid] = s;
    }

    // bitonic sort descending, 512 elements, 1 element/thread
    for (int k = 2; k <= NPG; k <<= 1) {
        for (int j = k >> 1; j > 0; j >>= 1) {
            __syncthreads();
            int i = tid;
            int ixj = i ^ j;
            if (ixj > i) {
                float a = so[i], b = so[ixj];
                bool dsc = ((i & k) == 0);
                if (dsc ? (a < b) : (a > b)) { so[i] = b; so[ixj] = a; }
            }
        }
    }
    __syncthreads();
    const float thr = so[KTOP - 1];     // K-th largest score

    // gated max pool: warp w owns features [8w, 8w+8)
    const int warp = tid >> 5, lane = tid & 31;
    const int f0 = warp * 8;
    float m[8];
#pragma unroll
    for (int j = 0; j < 8; j++) m[j] = -INFINITY;

    for (int n = lane; n < NPG; n += 32) {
        float s = sc[n];
        if (s >= thr) {
            float t = tanhf(s);
            const float4* r = (const float4*)(g_agg2 + (size_t)(g * NPG + n) * 128 + f0);
            float4 a = r[0], b = r[1];
            m[0] = fmaxf(m[0], a.x * t);
            m[1] = fmaxf(m[1], a.y * t);
            m[2] = fmaxf(m[2], a.z * t);
            m[3] = fmaxf(m[3], a.w * t);
            m[4] = fmaxf(m[4], b.x * t);
            m[5] = fmaxf(m[5], b.y * t);
            m[6] = fmaxf(m[6], b.z * t);
            m[7] = fmaxf(m[7], b.w * t);
        }
    }
#pragma unroll
    for (int o = 16; o > 0; o >>= 1) {
#pragma unroll
        for (int j = 0; j < 8; j++)
            m[j] = fmaxf(m[j], __shfl_xor_sync(0xffffffffu, m[j], o));
    }
    if (lane == 0) {
#pragma unroll
        for (int j = 0; j < 8; j++) gsh[f0 + j] = m[j];
    }
    __syncthreads();

    // FC: logits[c] = g . fcW[:,c] + fcb[c]
    if (tid < NC) {
        float acc = fcb[tid];
        for (int f = 0; f < 128; f++) acc += gsh[f] * fcW[f * NC + tid];
        lg[tid] = acc;
    }
    __syncthreads();
    if (tid == 0) {
        float mx = lg[0];
        for (int c = 1; c < NC; c++) mx = fmaxf(mx, lg[c]);
        float sum = 0.0f;
        for (int c = 0; c < NC; c++) sum += expf(lg[c] - mx);
        red2[0] = mx;
        red2[1] = logf(sum);
    }
    __syncthreads();
    if (tid < NC) out[g * NC + tid] = lg[tid] - red2[0] - red2[1];
}

// ---------------- launch: identify inputs by SIZE, not position ----------
// Element counts:
//   x=8388608 (f32), edge_index=1048576 (INT32 — JAX default disables x64),
//   batch=65536 (int32, unused), W1=W2=8192 (tie: W1 first), b1=64,
//   b2=pool_w=128 (tie: b2 first), fc_W=1280, fc_b=10.
// Both plausible metadata orderings (dict order and alphabetical) preserve
// W1-before-W2 and b2-before-pool_w, so first-occurrence tie-break is safe.
extern "C" void kernel_launch(void* const* d_in, const int* in_sizes, int n_in,
                              void* d_out, int out_size) {
    const float* x = 0;  const int* ei = 0;
    const float* W1 = 0; const float* b1 = 0;
    const float* W2 = 0; const float* b2 = 0;
    const float* pw = 0; const float* fcW = 0; const float* fcb = 0;

    for (int i = 0; i < n_in; i++) {
        int sz = in_sizes[i];
        const void* p = d_in[i];
        switch (sz) {
            case 8388608: x   = (const float*)p; break;       // 65536*128
            case 1048576: ei  = (const int*)p; break;         // 2*524288 int32
            case 65536:   /* batch: unused */ break;
            case 8192:    if (!W1) W1 = (const float*)p;      // 128*64
                          else     W2 = (const float*)p; break;// 64*128
            case 64:      b1  = (const float*)p; break;
            case 128:     if (!b2) b2 = (const float*)p;
                          else     pw = (const float*)p; break;
            case 1280:    fcW = (const float*)p; break;       // 128*10
            case 10:      fcb = (const float*)p; break;
            default: break;
        }
    }
    float* out = (float*)d_out;
    if (!x || !ei || !W1 || !W2 || !b1 || !b2 || !pw || !fcW || !fcb)
        return;   // detection failed: do nothing rather than trap

    // CSR build + degree normalization (atomic-free, per-graph blocks)
    k_csr<<<NG, 512>>>(ei);

    // conv1: dense transform + CSR gather (relu fused)
    k_gemm1<<<NT / 128, 128>>>(x, W1);
    k_gather1<<<NT * 32 / 256, 256>>>(b1);

    // conv2
    k_gemm2<<<dim3(NT / 128, 2), 128>>>(W2);
    k_gather2<<<NT * 32 / 256, 256>>>(b2);

    // topk-pool + gated max + FC + log_softmax
    k_pool<<<NG, 512>>>(pw, fcW, fcb, out);
}

// round 17
// speedup vs baseline: 1.6009x; 1.6009x over previous
#include <cuda_runtime.h>
#include <math.h>

// Problem constants (fixed shapes from reference)
#define NT   65536      // total nodes = 128*512
#define NE   524288     // edges (before self loops)
#define NG   128        // graphs
#define NPG  512        // nodes per graph
#define EPG  4096       // edges per graph (NE/NG)
#define KTOP 410        // ceil(0.8*512)
#define H1   64
#define H2   128
#define FIN  128
#define NC   10

#define NMASK (NT - 1)    // node index guard (power of 2)
#define EMASK (NE - 1)    // edge index guard (power of 2)

// ---------------- scratch (device globals; no runtime allocation) ----------
__device__ __align__(16) float g_dis[NT];      // rsqrt(degree), incl self loop
__device__ __align__(16) int   g_rowptr[NT];   // CSR row start (global edge idx)
__device__ __align__(16) int   g_rowend[NT];   // CSR row end
__device__ __align__(16) int   g_esrc[NE];     // CSR: src per in-edge (dst-grouped)
__device__ __align__(16) float g_h1[NT * H1];  // x @ W1
__device__ __align__(16) float g_agg1[NT * H1];// relu(conv1 out)
__device__ __align__(16) float g_h2[NT * H2];  // agg1 @ W2
__device__ __align__(16) float g_agg2[NT * H2];// relu(conv2 out)

// ---------------- per-graph CSR build: O(E) per block ----------------------
// edge_index is INT32. One block per graph; edges of graph g in ei[g*EPG..),
// ids in [g*NPG,(g+1)*NPG). Histogram via smem atomics (counts are order-
// independent => deterministic). Fill done by warp 0 with match_any: edges
// processed in index order, intra-round rank = lane order => deterministic
// CSR ordering => bit-stable float sums downstream.
__global__ __launch_bounds__(512) void k_csr(const int* __restrict__ ei) {
    __shared__ __align__(16) int s_src[EPG];
    __shared__ __align__(16) int s_dst[EPG];
    __shared__ int s_cnt[NPG];      // histogram, then fill cursor
    __shared__ int s_row[NPG];      // scan workspace
    const int g = blockIdx.x;
    const int t = threadIdx.x;
    const int ebase = g * EPG;
    const int nbase = g * NPG;

    s_cnt[t] = 0;
#pragma unroll
    for (int k = 0; k < EPG / 512; k++) {
        int e = t + k * 512;
        s_src[e] = (ei[ebase + e] - nbase) & (NPG - 1);
        s_dst[e] = (ei[NE + ebase + e] - nbase) & (NPG - 1);
    }
    __syncthreads();

    // histogram: 4096 smem atomics spread over 512 addresses
#pragma unroll
    for (int k = 0; k < EPG / 512; k++)
        atomicAdd(&s_cnt[s_dst[t + k * 512]], 1);
    __syncthreads();

    // exclusive scan over 512 degrees (Hillis-Steele)
    const int cnt = s_cnt[t];
    s_row[t] = cnt;
    __syncthreads();
    for (int off = 1; off < 512; off <<= 1) {
        int v = (t >= off) ? s_row[t - off] : 0;
        __syncthreads();
        s_row[t] += v;
        __syncthreads();
    }
    const int rloc = s_row[t] - cnt;              // local row start (0..4095)
    g_rowptr[nbase + t] = ebase + rloc;
    g_rowend[nbase + t] = ebase + rloc + cnt;
    g_dis[nbase + t] = rsqrtf((float)(cnt + 1));  // +1 self loop
    s_cnt[t] = rloc;                              // reuse as fill cursor
    __syncthreads();

    // warp 0: deterministic fill in edge order
    if (t < 32) {
        for (int r = 0; r < EPG / 32; r++) {
            int e = r * 32 + t;
            int d = s_dst[e];
            unsigned mm = __match_any_sync(0xffffffffu, d);
            int leader = __ffs(mm) - 1;
            int rank = __popc(mm & ((1u << t) - 1));
            int base = 0;
            if (t == leader) {                    // distinct d per leader: no race
                base = s_cnt[d];
                s_cnt[d] = base + __popc(mm);
            }
            base = __shfl_sync(0xffffffffu, base, leader);
            g_esrc[(ebase + base + rank) & EMASK] = nbase + s_src[e];
        }
    }
}

// ---------------- GEMM1: h1[NT,64] = x[NT,128] @ W1[128,64] ----------------
// 128 threads = 32 row-groups x 4 col-groups; thread owns 4 rows x 16 cols
// (cols strided: {16m+4cg}). Per k-step: 4 LDS.32 + 4 LDS.128 for 64 FMA.
__global__ __launch_bounds__(128) void k_gemm1(const float* __restrict__ x,
                                               const float* __restrict__ W) {
    __shared__ float Xs[128][33];
    __shared__ float Ws[32][64];
    const int tid = threadIdx.x;
    const int nb = blockIdx.x * 128;
    const int rg = tid >> 2, cg = tid & 3;

    float4 acc[4][4];
#pragma unroll
    for (int i = 0; i < 4; i++)
#pragma unroll
        for (int m = 0; m < 4; m++) acc[i][m] = make_float4(0.f, 0.f, 0.f, 0.f);

    for (int kc = 0; kc < 4; kc++) {   // K=128 in chunks of 32
#pragma unroll
        for (int it = 0; it < 8; it++) {
            int i = tid + it * 128;
            int row = i >> 3, q = i & 7;
            float4 v = ((const float4*)x)[(size_t)(nb + row) * 32 + kc * 8 + q];
            Xs[row][q * 4 + 0] = v.x;
            Xs[row][q * 4 + 1] = v.y;
            Xs[row][q * 4 + 2] = v.z;
            Xs[row][q * 4 + 3] = v.w;
        }
#pragma unroll
        for (int it = 0; it < 4; it++) {
            int i = tid + it * 128;
            int r = i >> 4, q = i & 15;
            float4 v = ((const float4*)W)[(size_t)(kc * 32 + r) * 16 + q];
            *(float4*)&Ws[r][q * 4] = v;
        }
        __syncthreads();

#pragma unroll 4
        for (int kk = 0; kk < 32; kk++) {
            float a0 = Xs[4 * rg + 0][kk];
            float a1 = Xs[4 * rg + 1][kk];
            float a2 = Xs[4 * rg + 2][kk];
            float a3 = Xs[4 * rg + 3][kk];
#pragma unroll
            for (int m = 0; m < 4; m++) {
                float4 w = *(const float4*)&Ws[kk][16 * m + 4 * cg];
                acc[0][m].x += a0 * w.x; acc[0][m].y += a0 * w.y;
                acc[0][m].z += a0 * w.z; acc[0][m].w += a0 * w.w;
                acc[1][m].x += a1 * w.x; acc[1][m].y += a1 * w.y;
                acc[1][m].z += a1 * w.z; acc[1][m].w += a1 * w.w;
                acc[2][m].x += a2 * w.x; acc[2][m].y += a2 * w.y;
                acc[2][m].z += a2 * w.z; acc[2][m].w += a2 * w.w;
                acc[3][m].x += a3 * w.x; acc[3][m].y += a3 * w.y;
                acc[3][m].z += a3 * w.z; acc[3][m].w += a3 * w.w;
            }
        }
        __syncthreads();
    }

#pragma unroll
    for (int i = 0; i < 4; i++)
#pragma unroll
        for (int m = 0; m < 4; m++)
            *(float4*)&g_h1[(size_t)(nb + 4 * rg + i) * 64 + 16 * m + 4 * cg] = acc[i][m];
}

// ---------------- gather1: agg1 = relu(self + bias + sum_e w*h1[src]) -----
// one warp per node; lane owns float2 (2 of 64 features)
__global__ __launch_bounds__(256) void k_gather1(const float* __restrict__ b1) {
    const int node = (blockIdx.x * 256 + threadIdx.x) >> 5;
    const int lane = threadIdx.x & 31;
    const int start = g_rowptr[node] & EMASK;
    int cnt = g_rowend[node] - g_rowptr[node];
    if (cnt < 0) cnt = 0; if (cnt > EPG) cnt = EPG;
    const int end = start + cnt;
    const float dd = g_dis[node];
    const float2* h = (const float2*)g_h1;

    float2 acc = h[(size_t)node * 32 + lane];
    float2 b   = ((const float2*)b1)[lane];
    acc.x = dd * dd * acc.x + b.x;
    acc.y = dd * dd * acc.y + b.y;

    int j = start;
    while (j < end) {
        int m = end - j; if (m > 8) m = 8;
        int sa[8]; float wa[8];
#pragma unroll
        for (int k = 0; k < 8; k++) sa[k] = (k < m) ? (g_esrc[(j + k) & EMASK] & NMASK) : 0;
#pragma unroll
        for (int k = 0; k < 8; k++) wa[k] = (k < m) ? dd * g_dis[sa[k]] : 0.0f;
#pragma unroll
        for (int k = 0; k < 8; k++) {
            float2 v = h[(size_t)sa[k] * 32 + lane];
            acc.x += wa[k] * v.x;
            acc.y += wa[k] * v.y;
        }
        j += m;
    }
    ((float2*)g_agg1)[(size_t)node * 32 + lane] =
        make_float2(fmaxf(acc.x, 0.0f), fmaxf(acc.y, 0.0f));
}

// ---------------- GEMM2: h2[NT,128] = agg1[NT,64] @ W2[64,128] ------------
// same register blocking; grid.y selects 64-col half
__global__ __launch_bounds__(128) void k_gemm2(const float* __restrict__ W2) {
    __shared__ float Xs[128][33];
    __shared__ float Ws[32][64];
    const int tid = threadIdx.x;
    const int nb = blockIdx.x * 128;
    const int cb = blockIdx.y * 64;
    const int rg = tid >> 2, cg = tid & 3;

    float4 acc[4][4];
#pragma unroll
    for (int i = 0; i < 4; i++)
#pragma unroll
        for (int m = 0; m < 4; m++) acc[i][m] = make_float4(0.f, 0.f, 0.f, 0.f);

    for (int kc = 0; kc < 2; kc++) {   // K=64 in chunks of 32
#pragma unroll
        for (int it = 0; it < 8; it++) {
            int i = tid + it * 128;
            int row = i >> 3, q = i & 7;
            float4 v = ((const float4*)g_agg1)[(size_t)(nb + row) * 16 + kc * 8 + q];
            Xs[row][q * 4 + 0] = v.x;
            Xs[row][q * 4 + 1] = v.y;
            Xs[row][q * 4 + 2] = v.z;
            Xs[row][q * 4 + 3] = v.w;
        }
#pragma unroll
        for (int it = 0; it < 4; it++) {
            int i = tid + it * 128;
            int r = i >> 4, q = i & 15;
            float4 v = ((const float4*)W2)[(size_t)(kc * 32 + r) * 32 + (cb >> 2) + q];
            *(float4*)&Ws[r][q * 4] = v;
        }
        __syncthreads();

#pragma unroll 4
        for (int kk = 0; kk < 32; kk++) {
            float a0 = Xs[4 * rg + 0][kk];
            float a1 = Xs[4 * rg + 1][kk];
            float a2 = Xs[4 * rg + 2][kk];
            float a3 = Xs[4 * rg + 3][kk];
#pragma unroll
            for (int m = 0; m < 4; m++) {
                float4 w = *(const float4*)&Ws[kk][16 * m + 4 * cg];
                acc[0][m].x += a0 * w.x; acc[0][m].y += a0 * w.y;
                acc[0][m].z += a0 * w.z; acc[0][m].w += a0 * w.w;
                acc[1][m].x += a1 * w.x; acc[1][m].y += a1 * w.y;
                acc[1][m].z += a1 * w.z; acc[1][m].w += a1 * w.w;
                acc[2][m].x += a2 * w.x; acc[2][m].y += a2 * w.y;
                acc[2][m].z += a2 * w.z; acc[2][m].w += a2 * w.w;
                acc[3][m].x += a3 * w.x; acc[3][m].y += a3 * w.y;
                acc[3][m].z += a3 * w.z; acc[3][m].w += a3 * w.w;
            }
        }
        __syncthreads();
    }

#pragma unroll
    for (int i = 0; i < 4; i++)
#pragma unroll
        for (int m = 0; m < 4; m++)
            *(float4*)&g_h2[(size_t)(nb + 4 * rg + i) * 128 + cb + 16 * m + 4 * cg] = acc[i][m];
}

// ---------------- gather2: agg2 = relu(self + bias + sum_e w*h2[src]) -----
// one warp per node; lane owns float4 (4 of 128 features)
__global__ __launch_bounds__(256) void k_gather2(const float* __restrict__ b2) {
    const int node = (blockIdx.x * 256 + threadIdx.x) >> 5;
    const int lane = threadIdx.x & 31;
    const int start = g_rowptr[node] & EMASK;
    int cnt = g_rowend[node] - g_rowptr[node];
    if (cnt < 0) cnt = 0; if (cnt > EPG) cnt = EPG;
    const int end = start + cnt;
    const float dd = g_dis[node];
    const float4* h = (const float4*)g_h2;

    float4 acc = h[(size_t)node * 32 + lane];
    float4 b   = ((const float4*)b2)[lane];
    float d2 = dd * dd;
    acc.x = d2 * acc.x + b.x;
    acc.y = d2 * acc.y + b.y;
    acc.z = d2 * acc.z + b.z;
    acc.w = d2 * acc.w + b.w;

    int j = start;
    while (j < end) {
        int m = end - j; if (m > 8) m = 8;
        int sa[8]; float wa[8];
#pragma unroll
        for (int k = 0; k < 8; k++) sa[k] = (k < m) ? (g_esrc[(j + k) & EMASK] & NMASK) : 0;
#pragma unroll
        for (int k = 0; k < 8; k++) wa[k] = (k < m) ? dd * g_dis[sa[k]] : 0.0f;
#pragma unroll
        for (int k = 0; k < 8; k++) {
            float4 v = h[(size_t)sa[k] * 32 + lane];
            acc.x += wa[k] * v.x;
            acc.y += wa[k] * v.y;
            acc.z += wa[k] * v.z;
            acc.w += wa[k] * v.w;
        }
        j += m;
    }
    ((float4*)g_agg2)[(size_t)node * 32 + lane] =
        make_float4(fmaxf(acc.x, 0.0f), fmaxf(acc.y, 0.0f),
                    fmaxf(acc.z, 0.0f), fmaxf(acc.w, 0.0f));
}

// ---------------- per-graph: score, top-K threshold, gated max, FC, lsm ---
__global__ __launch_bounds__(512) void k_pool(const float* __restrict__ pw,
                                              const float* __restrict__ fcW,
                                              const float* __restrict__ fcb,
                                              float* __restrict__ out) {
    __shared__ float pwsh[128];
    __shared__ float sc[NPG];
    __shared__ float so[NPG];
    __shared__ float gsh[128];
    __shared__ float lg[NC];
    __shared__ float red2[2];
    __shared__ float s_inv;

    const int tid = threadIdx.x;
    const int g = blockIdx.x;

    if (tid < 128) pwsh[tid] = pw[tid];
    __syncthreads();
    if (tid == 0) {
        float s = 0.0f;
        for (int f = 0; f < 128; f++) s += pwsh[f] * pwsh[f];
        s_inv = rsqrtf(s);
    }
    __syncthreads();

    {
        const float4* row = (const float4*)(g_agg2 + (size_t)(g * NPG + tid) * 128);
        float s = 0.0f;
#pragma unroll 8
        for (int i = 0; i < 32; i++) {
            float4 v = row[i];
            s += v.x * pwsh[4 * i + 0] + v.y * pwsh[4 * i + 1]
               + v.z * pwsh[4 * i + 2] + v.w * pwsh[4 * i + 3];
        }
        s *= s_inv;
        sc[tid] = s;
        so[tid] = s;
    }

    // bitonic sort descending, 512 elements
    for (int k = 2; k <= NPG; k <<= 1) {
        for (int j = k >> 1; j > 0; j >>= 1) {
            __syncthreads();
            int i = tid;
            int ixj = i ^ j;
            if (ixj > i) {
                float a = so[i], b = so[ixj];
                bool dsc = ((i & k) == 0);
                if (dsc ? (a < b) : (a > b)) { so[i] = b; so[ixj] = a; }
            }
        }
    }
    __syncthreads();
    const float thr = so[KTOP - 1];

    const int warp = tid >> 5, lane = tid & 31;
    const int f0 = warp * 8;
    float m[8];
#pragma unroll
    for (int j = 0; j < 8; j++) m[j] = -INFINITY;

    for (int n = lane; n < NPG; n += 32) {
        float s = sc[n];
        if (s >= thr) {
            float t = tanhf(s);
            const float4* r = (const float4*)(g_agg2 + (size_t)(g * NPG + n) * 128 + f0);
            float4 a = r[0], b = r[1];
            m[0] = fmaxf(m[0], a.x * t);
            m[1] = fmaxf(m[1], a.y * t);
            m[2] = fmaxf(m[2], a.z * t);
            m[3] = fmaxf(m[3], a.w * t);
            m[4] = fmaxf(m[4], b.x * t);
            m[5] = fmaxf(m[5], b.y * t);
            m[6] = fmaxf(m[6], b.z * t);
            m[7] = fmaxf(m[7], b.w * t);
        }
    }
#pragma unroll
    for (int o = 16; o > 0; o >>= 1) {
#pragma unroll
        for (int j = 0; j < 8; j++)
            m[j] = fmaxf(m[j], __shfl_xor_sync(0xffffffffu, m[j], o));
    }
    if (lane == 0) {
#pragma unroll
        for (int j = 0; j < 8; j++) gsh[f0 + j] = m[j];
    }
    __syncthreads();

    if (tid < NC) {
        float acc = fcb[tid];
        for (int f = 0; f < 128; f++) acc += gsh[f] * fcW[f * NC + tid];
        lg[tid] = acc;
    }
    __syncthreads();
    if (tid == 0) {
        float mx = lg[0];
        for (int c = 1; c < NC; c++) mx = fmaxf(mx, lg[c]);
        float sum = 0.0f;
        for (int c = 0; c < NC; c++) sum += expf(lg[c] - mx);
        red2[0] = mx;
        red2[1] = logf(sum);
    }
    __syncthreads();
    if (tid < NC) out[g * NC + tid] = lg[tid] - red2[0] - red2[1];
}

// ---------------- launch: identify inputs by SIZE, not position ----------
extern "C" void kernel_launch(void* const* d_in, const int* in_sizes, int n_in,
                              void* d_out, int out_size) {
    const float* x = 0;  const int* ei = 0;
    const float* W1 = 0; const float* b1 = 0;
    const float* W2 = 0; const float* b2 = 0;
    const float* pw = 0; const float* fcW = 0; const float* fcb = 0;

    for (int i = 0; i < n_in; i++) {
        int sz = in_sizes[i];
        const void* p = d_in[i];
        switch (sz) {
            case 8388608: x   = (const float*)p; break;       // 65536*128
            case 1048576: ei  = (const int*)p; break;         // 2*524288 int32
            case 65536:   /* batch: unused */ break;
            case 8192:    if (!W1) W1 = (const float*)p;      // 128*64
                          else     W2 = (const float*)p; break;// 64*128
            case 64:      b1  = (const float*)p; break;
            case 128:     if (!b2) b2 = (const float*)p;
                          else     pw = (const float*)p; break;
            case 1280:    fcW = (const float*)p; break;       // 128*10
            case 10:      fcb = (const float*)p; break;
            default: break;
        }
    }
    float* out = (float*)d_out;
    if (!x || !ei || !W1 || !W2 || !b1 || !b2 || !pw || !fcW || !fcb)
        return;

    k_csr<<<NG, 512>>>(ei);

    k_gemm1<<<NT / 128, 128>>>(x, W1);
    k_gather1<<<NT * 32 / 256, 256>>>(b1);

    k_gemm2<<<dim3(NT / 128, 2), 128>>>(W2);
    k_gather2<<<NT * 32 / 256, 256>>>(b2);

    k_pool<<<NG, 512>>>(pw, fcW, fcb, out);
}